// round 16
// baseline (speedup 1.0000x reference)
#include <cuda_runtime.h>
#include <cuda_fp16.h>
#include <cstdint>

// Problem constants
#define LSEQ  1024
#define BATCH 16
#define DIN   1024
#define NOUT  512
#define NLAY  4
#define MROWS (LSEQ*BATCH)   // 16384
#define KDIM  1024
#define NDIM  3072           // 6 * NOUT
#define NCH   64             // scan chunks
#define CH    16             // steps per chunk
#define NCHAIN 16384         // 2*B*NOUT

// GEMM: block 128x256, BK=64, 256 threads, 8 warps (2x4) of 64x64 tiles
#define GK    64
#define NKT   (KDIM/GK)      // 16
#define A_BUF_B 16384        // 4 planes x 128 rows x 32B
#define B_ROW_B 1056         // 264 uints (32B pad)
#define B_BUF_B (32 * B_ROW_B)   // 33792
#define SMEM_BYTES (2*A_BUF_B + 2*B_BUF_B)   // 100352

// Scratch (device globals: allocation-free)
__device__ __half   g_xh[MROWS * DIN];            // half x, permuted (in-place across layers)
__device__ unsigned g_wh[NLAY * (KDIM/2) * NDIM]; // pair-packed half2 W
__device__ __half   g_u [MROWS * NDIM];           // gate activations (fp16)
__device__ float    g_F [NCH * NCHAIN];
__device__ float    g_C [NCH * NCHAIN];

__device__ __forceinline__ float tanh_fast(float x) {
    float y;
    asm("tanh.approx.f32 %0, %1;" : "=f"(y) : "f"(x));
    return y;
}
// sigmoid via single-MUFU tanh identity: sig(x) = 0.5 + 0.5*tanh(0.5x)
__device__ __forceinline__ float sigmoid_fast(float x) {
    return fmaf(0.5f, tanh_fast(0.5f * x), 0.5f);
}
__device__ __forceinline__ uint32_t smem_u32(const void* p) {
    uint32_t a;
    asm("{ .reg .u64 t; cvta.to.shared.u64 t, %1; cvt.u32.u64 %0, t; }"
        : "=r"(a) : "l"(p));
    return a;
}
__device__ __forceinline__ void cp_async16(uint32_t dst, const void* src) {
    asm volatile("cp.async.cg.shared.global [%0], [%1], 16;"
                 :: "r"(dst), "l"(src) : "memory");
}
__device__ __forceinline__ unsigned packh2(float lo, float hi) {
    __half2 h = __floats2half2_rn(lo, hi);
    return *reinterpret_cast<unsigned*>(&h);
}
__device__ __forceinline__ void mma_f16(float c[4],
                                        unsigned a0, unsigned a1,
                                        unsigned a2, unsigned a3,
                                        unsigned b0, unsigned b1) {
    asm volatile(
        "mma.sync.aligned.m16n8k16.row.col.f32.f16.f16.f32 "
        "{%0,%1,%2,%3}, {%4,%5,%6,%7}, {%8,%9}, {%0,%1,%2,%3};"
        : "+f"(c[0]), "+f"(c[1]), "+f"(c[2]), "+f"(c[3])
        : "r"(a0), "r"(a1), "r"(a2), "r"(a3), "r"(b0), "r"(b1));
}
// position of even k-pair start within permuted+swizzled row
__device__ __forceinline__ int permpos_pair(int k, int row) {
    int pp = (k & 15) >> 1;
    return (k & ~15) + ((((pp & 3) ^ (row & 3))) << 2) + ((pp >> 2) << 1);
}

// ---------------------------------------------------------------------------
// Weight pre-pack (once): wh[l][p][n] = half2( W[l][2p][n], W[l][2p+1][n] )
// ---------------------------------------------------------------------------
__global__ void wconv_kernel(const float* __restrict__ W, unsigned* __restrict__ Wp) {
    int e = blockIdx.x * blockDim.x + threadIdx.x;
    int n4 = e % (NDIM / 4);
    int tmp = e / (NDIM / 4);
    int p = tmp % (KDIM / 2);
    int l = tmp / (KDIM / 2);
    const float* base = W + (size_t)l * KDIM * NDIM + (size_t)(2 * p) * NDIM + n4 * 4;
    float4 r0 = *reinterpret_cast<const float4*>(base);
    float4 r1 = *reinterpret_cast<const float4*>(base + NDIM);
    uint4 u;
    u.x = packh2(r0.x, r1.x);
    u.y = packh2(r0.y, r1.y);
    u.z = packh2(r0.z, r1.z);
    u.w = packh2(r0.w, r1.w);
    reinterpret_cast<uint4*>(Wp + ((size_t)l * (KDIM/2) + p) * NDIM)[n4] = u;
}

// ---------------------------------------------------------------------------
// Embedding gather -> permuted half x
// ---------------------------------------------------------------------------
__global__ void gather_kernel(const int* __restrict__ tok,
                              const float* __restrict__ emb,
                              __half* __restrict__ outH) {
    int e = blockIdx.x * blockDim.x + threadIdx.x;
    int row = e >> 8;
    int d4  = e & 255;
    int t = tok[row];
    float4 v = reinterpret_cast<const float4*>(emb + (size_t)t * DIN)[d4];
    int k0 = d4 * 4;
    __half2 h01 = __floats2half2_rn(v.x, v.y);
    __half2 h23 = __floats2half2_rn(v.z, v.w);
    __half* xr = outH + (size_t)row * DIN;
    *reinterpret_cast<__half2*>(xr + permpos_pair(k0, row))     = h01;
    *reinterpret_cast<__half2*>(xr + permpos_pair(k0 + 2, row)) = h23;
}

// ---------------------------------------------------------------------------
// FP16 GEMM: U = X(M,K)*W(K,N). mma.sync m16n8k16 f16 -> fp32 acc. BK=64.
// ---------------------------------------------------------------------------
__global__ void __launch_bounds__(256, 1)
gemm_f16_kernel(const __half* __restrict__ Xh,
                const unsigned* __restrict__ Wp,
                const float* __restrict__ bias,
                __half* __restrict__ U) {
    extern __shared__ char sm[];
    char* Abuf = sm;                    // 2 * A_BUF_B
    char* Bbuf = sm + 2 * A_BUF_B;      // 2 * B_BUF_B
    const uint32_t a_s = smem_u32(Abuf);
    const uint32_t b_s = smem_u32(Bbuf);

    const int tid  = threadIdx.x;
    const int lane = tid & 31;
    const int warp = tid >> 5;
    const int wm = warp >> 2;        // 0..1
    const int wn = warp & 3;         // 0..3
    const int q = lane >> 2;         // 0..7
    const int j = lane & 3;          // 0..3
    const int rowBase = blockIdx.y * 128;
    const int colBase = blockIdx.x * 256;

    const char* Ag = reinterpret_cast<const char*>(Xh + (size_t)rowBase * DIN);
    const unsigned* Bg = Wp + colBase;

    float acc[4][8][4];
    #pragma unroll
    for (int mf = 0; mf < 4; mf++)
        #pragma unroll
        for (int nf = 0; nf < 8; nf++)
            #pragma unroll
            for (int e = 0; e < 4; e++) acc[mf][nf][e] = 0.f;

    auto cpStage = [&](int buf, int kt) {
        // A: 128 rows x 128B = 1024 x 16B chunks (4/thread)
        #pragma unroll
        for (int t = 0; t < 4; t++) {
            int v = tid + t * 256;
            int r = v >> 3, c = v & 7;
            cp_async16(a_s + buf * A_BUF_B + (c >> 1) * 4096 + r * 32 + (c & 1) * 16,
                       Ag + (size_t)r * (DIN * 2) + kt * 128 + c * 16);
        }
        // B: 32 pair-rows x 64 chunks = 2048 x 16B chunks (8/thread)
        #pragma unroll
        for (int t = 0; t < 8; t++) {
            int v = tid + t * 256;
            int p = v >> 6, nc = v & 63;
            cp_async16(b_s + buf * B_BUF_B + p * B_ROW_B + nc * 16,
                       Bg + (size_t)(kt * 32 + p) * NDIM + nc * 4);
        }
        asm volatile("cp.async.commit_group;" ::: "memory");
    };

    cpStage(0, 0);
    int buf = 0;

    for (int kt = 0; kt < NKT; kt++) {
        asm volatile("cp.async.wait_group 0;" ::: "memory");
        __syncthreads();
        if (kt < NKT - 1) cpStage(buf ^ 1, kt + 1);

        #pragma unroll
        for (int s = 0; s < 4; s++) {
            const char* ab = Abuf + buf * A_BUF_B + s * 4096;
            uint2 alo[4], ahi[4];
            #pragma unroll
            for (int mf = 0; mf < 4; mf++) {
                int r = wm * 64 + mf * 16 + q;
                int sw = (j ^ (r & 3)) * 8;
                alo[mf] = *reinterpret_cast<const uint2*>(ab + r * 32 + sw);
                ahi[mf] = *reinterpret_cast<const uint2*>(ab + (r + 8) * 32 + sw);
            }
            const char* bb = Bbuf + buf * B_BUF_B + (s * 8 + j) * B_ROW_B
                           + (wn * 64 + q) * 4;
            unsigned b0[8], b1[8];
            #pragma unroll
            for (int nf = 0; nf < 8; nf++) {
                b0[nf] = *reinterpret_cast<const unsigned*>(bb + nf * 32);
                b1[nf] = *reinterpret_cast<const unsigned*>(bb + 4 * B_ROW_B + nf * 32);
            }
            #pragma unroll
            for (int mf = 0; mf < 4; mf++)
                #pragma unroll
                for (int nf = 0; nf < 8; nf++)
                    mma_f16(acc[mf][nf],
                            alo[mf].x, ahi[mf].x, alo[mf].y, ahi[mf].y,
                            b0[nf], b1[nf]);
        }
        buf ^= 1;
    }

    // Epilogue: warp's 64-col slice lies within one 512-col block (64 | 512)
    const int wcol = colBase + wn * 64;
    const int dir  = wcol / 1536;
    const int cm   = wcol - dir * 1536;
    int btype = 0;
    const float* bptr = bias;
    if (cm >= 1024)      { btype = 2; bptr = bias + 1024 + dir * 512 + (cm - 1024); }
    else if (cm >= 512)  { btype = 1; bptr = bias + dir * 512 + (cm - 512); }

    #pragma unroll
    for (int nf = 0; nf < 8; nf++) {
        const int coff = nf * 8 + 2 * j;
        float bv0 = 0.f, bv1 = 0.f;
        if (btype) { bv0 = bptr[coff]; bv1 = bptr[coff + 1]; }
        const int col = wcol + coff;
        #pragma unroll
        for (int mf = 0; mf < 4; mf++) {
            const int row0 = rowBase + wm * 64 + mf * 16 + q;
            float v0 = acc[mf][nf][0], v1 = acc[mf][nf][1];
            float v2 = acc[mf][nf][2], v3 = acc[mf][nf][3];
            if (btype) {
                v0 = sigmoid_fast(v0 + bv0);
                v1 = sigmoid_fast(v1 + bv1);
                v2 = sigmoid_fast(v2 + bv0);
                v3 = sigmoid_fast(v3 + bv1);
            }
            *reinterpret_cast<__half2*>(&U[(size_t)row0 * NDIM + col])
                = __floats2half2_rn(v0, v1);
            *reinterpret_cast<__half2*>(&U[(size_t)(row0 + 8) * NDIM + col])
                = __floats2half2_rn(v2, v3);
        }
    }
}

// ---------------------------------------------------------------------------
// SRU scan pass 1: per-chunk affine (F,C), 2 chains/thread, NCH=64 chunks.
// ---------------------------------------------------------------------------
__global__ void scan1_kernel(const __half* __restrict__ U,
                             float* __restrict__ Fo, float* __restrict__ Co) {
    const int idx = blockIdx.x * blockDim.x + threadIdx.x;  // 0..NCH*NCHAIN/2-1
    const int pairc = idx & (NCHAIN / 2 - 1);
    const int g = idx >> 13;
    const int chain = pairc * 2;
    const int dir = chain >> 13;
    const int b = (chain >> 9) & 15;
    const int i = chain & 511;

    const __half* u0 = U + (size_t)b * NDIM + dir * 1536 + i;
    const int ustep = BATCH * NDIM;

    float2 F = make_float2(1.f, 1.f), C = make_float2(0.f, 0.f);
    const int l0 = g * CH;
    #pragma unroll
    for (int t = 0; t < CH; t++) {
        const int l = dir ? (l0 + CH - 1 - t) : (l0 + t);
        const __half* up = u0 + (size_t)l * ustep;
        float2 xt = __half22float2(__ldg(reinterpret_cast<const __half2*>(up)));
        float2 f  = __half22float2(__ldg(reinterpret_cast<const __half2*>(up + 512)));
        C.x = f.x * C.x + (1.f - f.x) * xt.x;
        C.y = f.y * C.y + (1.f - f.y) * xt.y;
        F.x *= f.x;
        F.y *= f.y;
    }
    *reinterpret_cast<float2*>(&Fo[(size_t)(g * (NCHAIN/2) + pairc) * 2]) = F;
    *reinterpret_cast<float2*>(&Co[(size_t)(g * (NCHAIN/2) + pairc) * 2]) = C;
}

// ---------------------------------------------------------------------------
// SRU scan pass 2+3 fused: block = 4 pairs x 64 chunks (256 threads).
// Combine (4 threads, serial over 64 chunks in smem) replaces old scan2;
// then per-thread chunk recompute + emit h.
// ---------------------------------------------------------------------------
__global__ void __launch_bounds__(256)
scan3_kernel(const __half* __restrict__ U,
             const float* __restrict__ Fo, const float* __restrict__ Co,
             __half* __restrict__ Xh,      // in-place x (read xp / write h)
             float* __restrict__ OutF,     // non-null on last layer
             float* __restrict__ Cout) {
    __shared__ float2 sF[4][NCH], sC[4][NCH], sce[4][NCH];

    const int tid = threadIdx.x;
    const int p = tid & 3;           // local pair
    const int g = tid >> 2;          // chunk 0..63
    const int pairc = blockIdx.x * 4 + p;
    const int chain = pairc * 2;
    const int dir = chain >> 13;
    const int b = (chain >> 9) & 15;
    const int i = chain & 511;

    // load chunk summaries
    sF[p][g] = *reinterpret_cast<const float2*>(&Fo[(size_t)(g * (NCHAIN/2) + pairc) * 2]);
    sC[p][g] = *reinterpret_cast<const float2*>(&Co[(size_t)(g * (NCHAIN/2) + pairc) * 2]);
    __syncthreads();

    // combine: 4 threads, serial over chunks (dir-ordered)
    if (tid < 4) {
        const int pairc2 = blockIdx.x * 4 + tid;
        const int chain2 = pairc2 * 2;
        const int d2 = chain2 >> 13;
        float2 c = make_float2(0.f, 0.f);
        #pragma unroll
        for (int t = 0; t < NCH; t++) {
            int gg = d2 ? (NCH - 1 - t) : t;
            sce[tid][gg] = c;
            float2 Fv = sF[tid][gg], Cv = sC[tid][gg];
            c.x = Fv.x * c.x + Cv.x;
            c.y = Fv.y * c.y + Cv.y;
        }
        const int b2 = (chain2 >> 9) & 15;
        const int i2 = chain2 & 511;
        *reinterpret_cast<float2*>(&Cout[b2 * 1024 + d2 * 512 + i2]) = c;
    }
    __syncthreads();

    // pass 3: recompute with chunk-entry c, emit h
    const __half* u0 = U + (size_t)b * NDIM + dir * 1536 + i;
    const int ustep = BATCH * NDIM;
    const int xstep = BATCH * DIN;
    const int kk = dir * 512 + i;
    const size_t hposoff = (size_t)b * DIN + permpos_pair(kk, b);
    const size_t foff    = (size_t)b * DIN + dir * 512 + i;

    float2 c2 = sce[p][g];
    const int l0 = g * CH;
    #pragma unroll
    for (int t = 0; t < CH; t++) {
        const int l = dir ? (l0 + CH - 1 - t) : (l0 + t);
        const __half* up = u0 + (size_t)l * ustep;
        float2 xt = __half22float2(__ldg(reinterpret_cast<const __half2*>(up)));
        float2 f  = __half22float2(__ldg(reinterpret_cast<const __half2*>(up + 512)));
        float2 r  = __half22float2(__ldg(reinterpret_cast<const __half2*>(up + 1024)));
        __half2* xpp = reinterpret_cast<__half2*>(Xh + (size_t)l * xstep + hposoff);
        float2 xp = __half22float2(*xpp);
        c2.x = f.x * c2.x + (1.f - f.x) * xt.x;
        c2.y = f.y * c2.y + (1.f - f.y) * xt.y;
        float h0 = r.x * tanh_fast(c2.x) + (1.f - r.x) * xp.x;
        float h1 = r.y * tanh_fast(c2.y) + (1.f - r.y) * xp.y;
        if (OutF) {
            *reinterpret_cast<float2*>(&OutF[(size_t)l * xstep + foff])
                = make_float2(h0, h1);
        } else {
            *xpp = __floats2half2_rn(h0, h1);
        }
    }
}

// ---------------------------------------------------------------------------
// Launch
// ---------------------------------------------------------------------------
extern "C" void kernel_launch(void* const* d_in, const int* in_sizes, int n_in,
                              void* d_out, int out_size) {
    const int*   tok = (const int*)d_in[0];
    const float* emb = (const float*)d_in[2];
    const float* Ws  = (const float*)d_in[3];
    const float* bs  = (const float*)d_in[4];
    float* out = (float*)d_out;

    float *gF, *gC;
    __half *xh, *u;
    unsigned* wh;
    cudaGetSymbolAddress((void**)&xh, g_xh);
    cudaGetSymbolAddress((void**)&wh, g_wh);
    cudaGetSymbolAddress((void**)&u,  g_u);
    cudaGetSymbolAddress((void**)&gF, g_F);
    cudaGetSymbolAddress((void**)&gC, g_C);

    cudaFuncSetAttribute(gemm_f16_kernel,
                         cudaFuncAttributeMaxDynamicSharedMemorySize, SMEM_BYTES);

    // Pre-pack weights to half2 pairs
    wconv_kernel<<<(NLAY * (KDIM/2) * (NDIM/4)) / 256, 256>>>(Ws, wh);

    // Embedding gather
    gather_kernel<<<(MROWS * DIN / 4) / 256, 256>>>(tok, emb, xh);

    float* hid_base = out + (size_t)MROWS * DIN;

    dim3 ggrid(NDIM / 256, MROWS / 128);                 // (12, 128)
    const int scan1_blocks = (NCH * NCHAIN / 2) / 256;   // 2048
    const int scan3_blocks = (NCHAIN / 2) / 4;           // 2048

    for (int l = 0; l < NLAY; l++) {
        const unsigned* Wl = wh + (size_t)l * (KDIM/2) * NDIM;
        const float* bl = bs + (size_t)l * 2048;
        gemm_f16_kernel<<<ggrid, 256, SMEM_BYTES>>>(xh, Wl, bl, u);

        float* outF = (l == NLAY - 1) ? out : nullptr;
        float* cout_l = hid_base + (size_t)l * BATCH * DIN;

        scan1_kernel<<<scan1_blocks, 256>>>(u, gF, gC);
        scan3_kernel<<<scan3_blocks, 256>>>(u, gF, gC, xh, outF, cout_l);
    }
}

// round 17
// speedup vs baseline: 1.1585x; 1.1585x over previous
#include <cuda_runtime.h>
#include <cuda_fp16.h>
#include <cstdint>

// Problem constants
#define LSEQ  1024
#define BATCH 16
#define DIN   1024
#define NOUT  512
#define NLAY  4
#define MROWS (LSEQ*BATCH)   // 16384
#define KDIM  1024
#define NDIM  3072           // 6 * NOUT
#define NCH   32             // scan chunks
#define CH    32             // steps per chunk
#define NCHAIN 16384         // 2*B*NOUT

// GEMM: block 128x256, BK=64, 256 threads, 8 warps (2x4) of 64x64 tiles
#define GK    64
#define NKT   (KDIM/GK)      // 16
#define A_BUF_B 16384        // 4 planes x 128 rows x 32B
#define B_ROW_B 2080         // 256 uint2 + 32B pad
#define B_BUF_B (16 * B_ROW_B)   // 33280 (16 interleaved rows/stage)
#define SMEM_BYTES (2*A_BUF_B + 2*B_BUF_B)   // 99328

// Scratch (device globals: allocation-free)
__device__ __half   g_xh[MROWS * DIN];            // half x, permuted (in-place across layers)
__device__ uint2    g_wh[NLAY * 256 * NDIM];      // interleaved pair-packed W
__device__ __half   g_u [MROWS * NDIM];           // gate activations (fp16)
__device__ float    g_F [NCH * NCHAIN];
__device__ float    g_C [NCH * NCHAIN];
__device__ float    g_ce[NCH * NCHAIN];

__device__ __forceinline__ float tanh_fast(float x) {
    float y;
    asm("tanh.approx.f32 %0, %1;" : "=f"(y) : "f"(x));
    return y;
}
// sigmoid via single-MUFU tanh identity: sig(x) = 0.5 + 0.5*tanh(0.5x)
__device__ __forceinline__ float sigmoid_fast(float x) {
    return fmaf(0.5f, tanh_fast(0.5f * x), 0.5f);
}
__device__ __forceinline__ uint32_t smem_u32(const void* p) {
    uint32_t a;
    asm("{ .reg .u64 t; cvta.to.shared.u64 t, %1; cvt.u32.u64 %0, t; }"
        : "=r"(a) : "l"(p));
    return a;
}
__device__ __forceinline__ void cp_async16(uint32_t dst, const void* src) {
    asm volatile("cp.async.cg.shared.global [%0], [%1], 16;"
                 :: "r"(dst), "l"(src) : "memory");
}
__device__ __forceinline__ unsigned packh2(float lo, float hi) {
    __half2 h = __floats2half2_rn(lo, hi);
    return *reinterpret_cast<unsigned*>(&h);
}
__device__ __forceinline__ void mma_f16(float c[4],
                                        unsigned a0, unsigned a1,
                                        unsigned a2, unsigned a3,
                                        unsigned b0, unsigned b1) {
    asm volatile(
        "mma.sync.aligned.m16n8k16.row.col.f32.f16.f16.f32 "
        "{%0,%1,%2,%3}, {%4,%5,%6,%7}, {%8,%9}, {%0,%1,%2,%3};"
        : "+f"(c[0]), "+f"(c[1]), "+f"(c[2]), "+f"(c[3])
        : "r"(a0), "r"(a1), "r"(a2), "r"(a3), "r"(b0), "r"(b1));
}
// position of even k-pair start within permuted+swizzled row
__device__ __forceinline__ int permpos_pair(int k, int row) {
    int pp = (k & 15) >> 1;
    return (k & ~15) + ((((pp & 3) ^ (row & 3))) << 2) + ((pp >> 2) << 1);
}

// ---------------------------------------------------------------------------
// Weight pre-pack (once), INTERLEAVED partner rows:
//   row rr = kt*16 + s*4 + j  (rr = 0..255) holds pairs p1 = kt*32+s*8+j and
//   p2 = p1+4:  Wp[(l*256+rr)*NDIM + n] = uint2{ h2(W[2p1][n],W[2p1+1][n]),
//                                                h2(W[2p2][n],W[2p2+1][n]) }
// ---------------------------------------------------------------------------
__global__ void wconv_kernel(const float* __restrict__ W, uint2* __restrict__ Wp) {
    int e = blockIdx.x * blockDim.x + threadIdx.x;   // over NLAY*256*768
    int n4 = e % (NDIM / 4);
    int tmp = e / (NDIM / 4);
    int rr = tmp % 256;
    int l  = tmp / 256;
    int p1 = (rr >> 4) * 32 + ((rr >> 2) & 3) * 8 + (rr & 3);
    int p2 = p1 + 4;
    const float* base = W + (size_t)l * KDIM * NDIM + (size_t)n4 * 4;
    float4 a0 = *reinterpret_cast<const float4*>(base + (size_t)(2 * p1)     * NDIM);
    float4 a1 = *reinterpret_cast<const float4*>(base + (size_t)(2 * p1 + 1) * NDIM);
    float4 c0 = *reinterpret_cast<const float4*>(base + (size_t)(2 * p2)     * NDIM);
    float4 c1 = *reinterpret_cast<const float4*>(base + (size_t)(2 * p2 + 1) * NDIM);
    uint2* dst = Wp + ((size_t)(l * 256 + rr) * NDIM + n4 * 4);
    dst[0] = make_uint2(packh2(a0.x, a1.x), packh2(c0.x, c1.x));
    dst[1] = make_uint2(packh2(a0.y, a1.y), packh2(c0.y, c1.y));
    dst[2] = make_uint2(packh2(a0.z, a1.z), packh2(c0.z, c1.z));
    dst[3] = make_uint2(packh2(a0.w, a1.w), packh2(c0.w, c1.w));
}

// ---------------------------------------------------------------------------
// Embedding gather -> permuted half x
// ---------------------------------------------------------------------------
__global__ void gather_kernel(const int* __restrict__ tok,
                              const float* __restrict__ emb,
                              __half* __restrict__ outH) {
    int e = blockIdx.x * blockDim.x + threadIdx.x;
    int row = e >> 8;
    int d4  = e & 255;
    int t = tok[row];
    float4 v = reinterpret_cast<const float4*>(emb + (size_t)t * DIN)[d4];
    int k0 = d4 * 4;
    __half2 h01 = __floats2half2_rn(v.x, v.y);
    __half2 h23 = __floats2half2_rn(v.z, v.w);
    __half* xr = outH + (size_t)row * DIN;
    *reinterpret_cast<__half2*>(xr + permpos_pair(k0, row))     = h01;
    *reinterpret_cast<__half2*>(xr + permpos_pair(k0 + 2, row)) = h23;
}

// ---------------------------------------------------------------------------
// FP16 GEMM: U = X(M,K)*W(K,N). mma.sync m16n8k16 f16 -> fp32 acc. BK=64.
// A smem: 4 k16-planes of 4096B; row r 32B: chunk j' = j^(r&3) 8B
// B smem: 16 interleaved rows (s*4+j) x 256 uint2, stride 2080B;
//         one LDS.64 yields (b0,b1) for an (n, s, j) triple. Conflict-free.
// ---------------------------------------------------------------------------
__global__ void __launch_bounds__(256, 1)
gemm_f16_kernel(const __half* __restrict__ Xh,
                const uint2* __restrict__ Wp,
                const float* __restrict__ bias,
                __half* __restrict__ U) {
    extern __shared__ char sm[];
    char* Abuf = sm;                    // 2 * A_BUF_B
    char* Bbuf = sm + 2 * A_BUF_B;      // 2 * B_BUF_B
    const uint32_t a_s = smem_u32(Abuf);
    const uint32_t b_s = smem_u32(Bbuf);

    const int tid  = threadIdx.x;
    const int lane = tid & 31;
    const int warp = tid >> 5;
    const int wm = warp >> 2;        // 0..1
    const int wn = warp & 3;         // 0..3
    const int q = lane >> 2;         // 0..7
    const int j = lane & 3;          // 0..3
    const int rowBase = blockIdx.y * 128;
    const int colBase = blockIdx.x * 256;

    const char* Ag = reinterpret_cast<const char*>(Xh + (size_t)rowBase * DIN);
    const uint2* Bg = Wp + colBase;

    float acc[4][8][4];
    #pragma unroll
    for (int mf = 0; mf < 4; mf++)
        #pragma unroll
        for (int nf = 0; nf < 8; nf++)
            #pragma unroll
            for (int e = 0; e < 4; e++) acc[mf][nf][e] = 0.f;

    auto cpStage = [&](int buf, int kt) {
        // A: 128 rows x 128B = 1024 x 16B chunks (4/thread)
        #pragma unroll
        for (int t = 0; t < 4; t++) {
            int v = tid + t * 256;
            int r = v >> 3, c = v & 7;
            cp_async16(a_s + buf * A_BUF_B + (c >> 1) * 4096 + r * 32 + (c & 1) * 16,
                       Ag + (size_t)r * (DIN * 2) + kt * 128 + c * 16);
        }
        // B: 16 rows x 128 chunks = 2048 x 16B chunks (8/thread)
        #pragma unroll
        for (int t = 0; t < 8; t++) {
            int v = tid + t * 256;
            int rr = v >> 7, c = v & 127;
            cp_async16(b_s + buf * B_BUF_B + rr * B_ROW_B + c * 16,
                       Bg + (size_t)(kt * 16 + rr) * NDIM + c * 2);
        }
        asm volatile("cp.async.commit_group;" ::: "memory");
    };

    cpStage(0, 0);
    int buf = 0;

    for (int kt = 0; kt < NKT; kt++) {
        asm volatile("cp.async.wait_group 0;" ::: "memory");
        __syncthreads();
        if (kt < NKT - 1) cpStage(buf ^ 1, kt + 1);

        #pragma unroll
        for (int s = 0; s < 4; s++) {
            const char* ab = Abuf + buf * A_BUF_B + s * 4096;
            uint2 alo[4], ahi[4];
            #pragma unroll
            for (int mf = 0; mf < 4; mf++) {
                int r = wm * 64 + mf * 16 + q;
                int sw = (j ^ (r & 3)) * 8;
                alo[mf] = *reinterpret_cast<const uint2*>(ab + r * 32 + sw);
                ahi[mf] = *reinterpret_cast<const uint2*>(ab + (r + 8) * 32 + sw);
            }
            const char* bb = Bbuf + buf * B_BUF_B + (s * 4 + j) * B_ROW_B
                           + (wn * 64 + q) * 8;
            uint2 bv[8];
            #pragma unroll
            for (int nf = 0; nf < 8; nf++)
                bv[nf] = *reinterpret_cast<const uint2*>(bb + nf * 64);
            #pragma unroll
            for (int mf = 0; mf < 4; mf++)
                #pragma unroll
                for (int nf = 0; nf < 8; nf++)
                    mma_f16(acc[mf][nf],
                            alo[mf].x, ahi[mf].x, alo[mf].y, ahi[mf].y,
                            bv[nf].x, bv[nf].y);
        }
        buf ^= 1;
    }

    // Epilogue: warp's 64-col slice lies within one 512-col block (64 | 512)
    const int wcol = colBase + wn * 64;
    const int dir  = wcol / 1536;
    const int cm   = wcol - dir * 1536;
    int btype = 0;
    const float* bptr = bias;
    if (cm >= 1024)      { btype = 2; bptr = bias + 1024 + dir * 512 + (cm - 1024); }
    else if (cm >= 512)  { btype = 1; bptr = bias + dir * 512 + (cm - 512); }

    #pragma unroll
    for (int nf = 0; nf < 8; nf++) {
        const int coff = nf * 8 + 2 * j;
        float bv0 = 0.f, bv1 = 0.f;
        if (btype) { bv0 = bptr[coff]; bv1 = bptr[coff + 1]; }
        const int col = wcol + coff;
        #pragma unroll
        for (int mf = 0; mf < 4; mf++) {
            const int row0 = rowBase + wm * 64 + mf * 16 + q;
            float v0 = acc[mf][nf][0], v1 = acc[mf][nf][1];
            float v2 = acc[mf][nf][2], v3 = acc[mf][nf][3];
            if (btype) {
                v0 = sigmoid_fast(v0 + bv0);
                v1 = sigmoid_fast(v1 + bv1);
                v2 = sigmoid_fast(v2 + bv0);
                v3 = sigmoid_fast(v3 + bv1);
            }
            *reinterpret_cast<__half2*>(&U[(size_t)row0 * NDIM + col])
                = __floats2half2_rn(v0, v1);
            *reinterpret_cast<__half2*>(&U[(size_t)(row0 + 8) * NDIM + col])
                = __floats2half2_rn(v2, v3);
        }
    }
}

// ---------------------------------------------------------------------------
// Chunked SRU scan (3-pass), 2 chains per thread via half2, NCH=32 chunks.
// (round-14 proven structure)
// ---------------------------------------------------------------------------
__global__ void scan1_kernel(const __half* __restrict__ U,
                             float* __restrict__ Fo, float* __restrict__ Co) {
    const int idx = blockIdx.x * blockDim.x + threadIdx.x;
    const int pairc = idx & (NCHAIN / 2 - 1);
    const int g = idx >> 13;
    const int chain = pairc * 2;
    const int dir = chain >> 13;
    const int b = (chain >> 9) & 15;
    const int i = chain & 511;

    const __half* u0 = U + (size_t)b * NDIM + dir * 1536 + i;
    const int ustep = BATCH * NDIM;

    float2 F = make_float2(1.f, 1.f), C = make_float2(0.f, 0.f);
    const int l0 = g * CH;
    #pragma unroll 8
    for (int t = 0; t < CH; t++) {
        const int l = dir ? (l0 + CH - 1 - t) : (l0 + t);
        const __half* up = u0 + (size_t)l * ustep;
        float2 xt = __half22float2(__ldg(reinterpret_cast<const __half2*>(up)));
        float2 f  = __half22float2(__ldg(reinterpret_cast<const __half2*>(up + 512)));
        C.x = f.x * C.x + (1.f - f.x) * xt.x;
        C.y = f.y * C.y + (1.f - f.y) * xt.y;
        F.x *= f.x;
        F.y *= f.y;
    }
    *reinterpret_cast<float2*>(&Fo[idx * 2]) = F;
    *reinterpret_cast<float2*>(&Co[idx * 2]) = C;
}

__global__ void scan2_kernel(const float* __restrict__ Fo, const float* __restrict__ Co,
                             float* __restrict__ ce, float* __restrict__ Cout) {
    const int chain = blockIdx.x * blockDim.x + threadIdx.x;
    const int dir = chain >> 13;
    const int b = (chain >> 9) & 15;
    const int i = chain & 511;

    float c = 0.f;
    #pragma unroll
    for (int t = 0; t < NCH; t++) {
        int g = dir ? (NCH - 1 - t) : t;
        ce[g * NCHAIN + chain] = c;
        c = Fo[g * NCHAIN + chain] * c + Co[g * NCHAIN + chain];
    }
    Cout[b * 1024 + dir * 512 + i] = c;
}

__global__ void scan3_kernel(const __half* __restrict__ U,
                             const float* __restrict__ ce,
                             __half* __restrict__ Xh,      // in-place x (read xp / write h)
                             float* __restrict__ OutF) {   // non-null on last layer
    const int idx = blockIdx.x * blockDim.x + threadIdx.x;
    const int pairc = idx & (NCHAIN / 2 - 1);
    const int g = idx >> 13;
    const int chain = pairc * 2;
    const int dir = chain >> 13;
    const int b = (chain >> 9) & 15;
    const int i = chain & 511;

    const __half* u0 = U + (size_t)b * NDIM + dir * 1536 + i;
    const int ustep = BATCH * NDIM;
    const int xstep = BATCH * DIN;

    const int kk = dir * 512 + i;
    const size_t hposoff = (size_t)b * DIN + permpos_pair(kk, b);
    const size_t foff    = (size_t)b * DIN + dir * 512 + i;

    float2 c2 = *reinterpret_cast<const float2*>(&ce[g * NCHAIN + chain]);
    const int l0 = g * CH;
    #pragma unroll 8
    for (int t = 0; t < CH; t++) {
        const int l = dir ? (l0 + CH - 1 - t) : (l0 + t);
        const __half* up = u0 + (size_t)l * ustep;
        float2 xt = __half22float2(__ldg(reinterpret_cast<const __half2*>(up)));
        float2 f  = __half22float2(__ldg(reinterpret_cast<const __half2*>(up + 512)));
        float2 r  = __half22float2(__ldg(reinterpret_cast<const __half2*>(up + 1024)));
        __half2* xpp = reinterpret_cast<__half2*>(Xh + (size_t)l * xstep + hposoff);
        float2 xp = __half22float2(*xpp);
        c2.x = f.x * c2.x + (1.f - f.x) * xt.x;
        c2.y = f.y * c2.y + (1.f - f.y) * xt.y;
        float h0 = r.x * tanh_fast(c2.x) + (1.f - r.x) * xp.x;
        float h1 = r.y * tanh_fast(c2.y) + (1.f - r.y) * xp.y;
        if (OutF) {
            *reinterpret_cast<float2*>(&OutF[(size_t)l * xstep + foff])
                = make_float2(h0, h1);
        } else {
            *xpp = __floats2half2_rn(h0, h1);
        }
    }
}

// ---------------------------------------------------------------------------
// Launch
// ---------------------------------------------------------------------------
extern "C" void kernel_launch(void* const* d_in, const int* in_sizes, int n_in,
                              void* d_out, int out_size) {
    const int*   tok = (const int*)d_in[0];
    const float* emb = (const float*)d_in[2];
    const float* Ws  = (const float*)d_in[3];
    const float* bs  = (const float*)d_in[4];
    float* out = (float*)d_out;

    float *gF, *gC, *gce;
    __half *xh, *u;
    uint2* wh;
    cudaGetSymbolAddress((void**)&xh, g_xh);
    cudaGetSymbolAddress((void**)&wh, g_wh);
    cudaGetSymbolAddress((void**)&u,  g_u);
    cudaGetSymbolAddress((void**)&gF, g_F);
    cudaGetSymbolAddress((void**)&gC, g_C);
    cudaGetSymbolAddress((void**)&gce, g_ce);

    cudaFuncSetAttribute(gemm_f16_kernel,
                         cudaFuncAttributeMaxDynamicSharedMemorySize, SMEM_BYTES);

    // Pre-pack weights (interleaved partner rows)
    wconv_kernel<<<(NLAY * 256 * (NDIM / 4)) / 256, 256>>>(Ws, wh);

    // Embedding gather
    gather_kernel<<<(MROWS * DIN / 4) / 256, 256>>>(tok, emb, xh);

    float* hid_base = out + (size_t)MROWS * DIN;

    dim3 ggrid(NDIM / 256, MROWS / 128);                 // (12, 128)
    const int scan13_blocks = (NCH * NCHAIN / 2) / 256;  // 1024

    for (int l = 0; l < NLAY; l++) {
        const uint2* Wl = wh + (size_t)l * 256 * NDIM;
        const float* bl = bs + (size_t)l * 2048;
        gemm_f16_kernel<<<ggrid, 256, SMEM_BYTES>>>(xh, Wl, bl, u);

        float* outF = (l == NLAY - 1) ? out : nullptr;
        float* cout_l = hid_base + (size_t)l * BATCH * DIN;

        scan1_kernel<<<scan13_blocks, 256>>>(u, gF, gC);
        scan2_kernel<<<NCHAIN / 256, 256>>>(gF, gC, gce, cout_l);
        scan3_kernel<<<scan13_blocks, 256>>>(u, gce, xh, outF);
    }
}